// round 11
// baseline (speedup 1.0000x reference)
#include <cuda_runtime.h>
#include <cuda_fp16.h>
#include <cstdint>
#include <math.h>

#define BATCH 8192
#define HID   1024
#define FOURH 4096
#define NLAYERS 4

// ---------------------------------------------------------------------------
// Scratch (allocation-free). Ping-pong activation buffers (cross-CTA safety).
// ---------------------------------------------------------------------------
__device__ __half g_A0[(size_t)BATCH * HID];
__device__ __half g_A1[(size_t)BATCH * HID];
__device__ __half g_W16[(size_t)NLAYERS * FOURH * HID];   // gate-permuted, transposed

// ---------------------------------------------------------------------------
// PTX helpers (arch-agnostic: sm_80+)
// ---------------------------------------------------------------------------
__device__ __forceinline__ uint32_t smem_u32(const void* p) {
    uint32_t a;
    asm("{ .reg .u64 t; cvta.to.shared.u64 t, %1; cvt.u32.u64 %0, t; }" : "=r"(a) : "l"(p));
    return a;
}
__device__ __forceinline__ void cp_async16(uint32_t sdst, const void* gsrc) {
    asm volatile("cp.async.cg.shared.global [%0], [%1], 16;" :: "r"(sdst), "l"(gsrc));
}
__device__ __forceinline__ void cp_commit() { asm volatile("cp.async.commit_group;"); }
template <int N>
__device__ __forceinline__ void cp_wait() { asm volatile("cp.async.wait_group %0;" :: "n"(N)); }

__device__ __forceinline__ void ldm_x4(uint32_t* r, uint32_t addr) {
    asm volatile("ldmatrix.sync.aligned.m8n8.x4.shared.b16 {%0,%1,%2,%3}, [%4];"
                 : "=r"(r[0]), "=r"(r[1]), "=r"(r[2]), "=r"(r[3]) : "r"(addr));
}
__device__ __forceinline__ void mma16816(float* c, const uint32_t* a, const uint32_t* b) {
    asm volatile(
        "mma.sync.aligned.m16n8k16.row.col.f32.f16.f16.f32 "
        "{%0,%1,%2,%3}, {%4,%5,%6,%7}, {%8,%9}, {%0,%1,%2,%3};"
        : "+f"(c[0]), "+f"(c[1]), "+f"(c[2]), "+f"(c[3])
        : "r"(a[0]), "r"(a[1]), "r"(a[2]), "r"(a[3]), "r"(b[0]), "r"(b[1]));
}
__device__ __forceinline__ void sts64(uint32_t addr, float x, float y) {
    asm volatile("st.shared.v2.f32 [%0], {%1, %2};" :: "r"(addr), "f"(x), "f"(y));
}
__device__ __forceinline__ float4 lds128(uint32_t addr) {
    float4 v;
    asm volatile("ld.shared.v4.f32 {%0,%1,%2,%3}, [%4];"
                 : "=f"(v.x), "=f"(v.y), "=f"(v.z), "=f"(v.w) : "r"(addr));
    return v;
}

// ---------------------------------------------------------------------------
// GEMM + fused LSTM gate epilogue + fused next-layer fp16 convert.
// C = A @ W16^T, single fp16 product. CTA tile 128x128, 8 warps (4Mx2N),
// warp tile 32x64. 1 CTA/SM, 255-reg budget, 4-stage cp.async pipeline,
// register-level fragment double-buffering (LDSM hidden under MMA).
// K chunks of 64 fp16, XOR-swizzled 128B rows (c -> c ^ (row&7)).
// Epilogue stages z in smem (528B row stride) for coalesced gmem I/O.
// ---------------------------------------------------------------------------
#define KC        64
#define NCHUNKS   (HID / KC)               // 16
#define ROWB      128
#define REG_B     (128 * ROWB)             // 16384 B per region
#define STAGE_B   (2 * REG_B)              // 32768 B (A, W)
#define NSTAGES   4
#define ZROWB     528                      // epilogue fp32 row stride
#define GEMM_SMEM (NSTAGES * STAGE_B)      // 131072 B (epilogue needs 67584)

__device__ __forceinline__ void load_region(const __half* g, int row0, int k0,
                                            uint32_t sdst, int tid) {
    const int row  = tid >> 1;
    const int half = tid & 1;
    const __half* src = g + (size_t)(row0 + row) * HID + k0 + half * 32;
    const uint32_t rbase = sdst + (uint32_t)row * ROWB;
    const int rm = row & 7;
    #pragma unroll
    for (int q = 0; q < 4; q++) {
        const int chunk = half * 4 + q;
        cp_async16(rbase + (uint32_t)((chunk ^ rm) << 4), src + q * 8);
    }
}

__global__ __launch_bounds__(256, 1) void gemm_lstm_fused(
    const __half* __restrict__ A,
    const __half* __restrict__ Wh,
    const float* __restrict__ bias,       // [4H] original layout
    const float* __restrict__ rowx,       // [B] or nullptr (layer-0 x)
    const float* __restrict__ colw,       // [4H] or nullptr (layer-0 Wx0)
    const float* __restrict__ c_prev,     // [B,H]
    float* __restrict__ c_out,            // [B,H]
    float* __restrict__ h_out,            // [B,H]
    __half* __restrict__ nA)              // next-layer A (ping-pong buf)
{
    extern __shared__ char smem[];
    const uint32_t sb = smem_u32(smem);

    const int tid    = threadIdx.x;
    const int wid    = tid >> 5;
    const int lane   = tid & 31;
    const int warp_m = wid & 3;
    const int warp_n = wid >> 2;
    const int bm = blockIdx.y * 128;
    const int bn = blockIdx.x * 128;

    const uint32_t swz   = (uint32_t)(lane & 7) << 4;
    const int      arow  = lane & 15;
    const uint32_t acol  = (uint32_t)(lane >> 4) * 16;
    const int      brow  = ((lane >> 4) << 3) | (lane & 7);
    const uint32_t bcol  = (uint32_t)((lane >> 3) & 1) * 16;

    const uint32_t aRowOff = (uint32_t)(warp_m * 32 + arow) * ROWB;
    const uint32_t bRowOff = (uint32_t)(warp_n * 64 + brow) * ROWB;

    float acc[2][8][4];
    #pragma unroll
    for (int mt = 0; mt < 2; mt++)
        #pragma unroll
        for (int nt = 0; nt < 8; nt++)
            #pragma unroll
            for (int q = 0; q < 4; q++) acc[mt][nt][q] = 0.f;

    // ---- prologue: fill stages 0..2 ----
    #pragma unroll
    for (int s = 0; s < NSTAGES - 1; s++) {
        const uint32_t sbuf = sb + (uint32_t)s * STAGE_B;
        load_region(A,  bm, s * KC, sbuf, tid);
        load_region(Wh, bn, s * KC, sbuf + REG_B, tid);
        cp_commit();
    }

    // double-buffered fragments
    uint32_t ah[2][2][4], bh[2][4][4];

    for (int c = 0; c < NCHUNKS; ++c) {
        if (c + NSTAGES - 1 < NCHUNKS) {
            const uint32_t sbuf = sb + (uint32_t)((c + NSTAGES - 1) & (NSTAGES - 1)) * STAGE_B;
            load_region(A,  bm, (c + NSTAGES - 1) * KC, sbuf, tid);
            load_region(Wh, bn, (c + NSTAGES - 1) * KC, sbuf + REG_B, tid);
        }
        cp_commit();                       // empty group when no loads: keeps accounting uniform
        cp_wait<NSTAGES - 1>();            // stage c complete
        __syncthreads();

        const uint32_t base  = sb + (uint32_t)(c & (NSTAGES - 1)) * STAGE_B;
        const uint32_t aBase = base + aRowOff;
        const uint32_t bBase = base + REG_B + bRowOff;

        // load ks=0 fragments into buffer 0
        {
            const uint32_t aOff = acol ^ swz;
            const uint32_t bOff = bcol ^ swz;
            #pragma unroll
            for (int np = 0; np < 4; np++)
                ldm_x4(bh[0][np], bBase + (uint32_t)np * 16 * ROWB + bOff);
            #pragma unroll
            for (int mt = 0; mt < 2; mt++)
                ldm_x4(ah[0][mt], aBase + (uint32_t)mt * 16 * ROWB + aOff);
        }

        #pragma unroll
        for (int ks = 0; ks < 4; ks++) {
            const int cur = ks & 1;
            const int nxt = cur ^ 1;
            if (ks < 3) {   // prefetch ks+1 fragments before the mma burst
                const uint32_t ko = (uint32_t)(ks + 1) * 32;
                const uint32_t aOff = (acol + ko) ^ swz;
                const uint32_t bOff = (bcol + ko) ^ swz;
                #pragma unroll
                for (int np = 0; np < 4; np++)
                    ldm_x4(bh[nxt][np], bBase + (uint32_t)np * 16 * ROWB + bOff);
                #pragma unroll
                for (int mt = 0; mt < 2; mt++)
                    ldm_x4(ah[nxt][mt], aBase + (uint32_t)mt * 16 * ROWB + aOff);
            }
            #pragma unroll
            for (int mt = 0; mt < 2; mt++)
                #pragma unroll
                for (int nt = 0; nt < 8; nt++)
                    mma16816(acc[mt][nt], ah[cur][mt], &bh[cur][nt >> 1][(nt & 1) * 2]);
        }
        __syncthreads();                   // all reads of stage c done before reuse
    }

    // ---- epilogue phase 1: stage z tile to smem (row stride 528B) ----
    {
        const int quad = lane >> 2;
        const uint32_t ncol = (uint32_t)(warp_n * 64 + 2 * (lane & 3)) * 4;
        #pragma unroll
        for (int mt = 0; mt < 2; mt++) {
            const uint32_t m0 = (uint32_t)(warp_m * 32 + mt * 16 + quad);
            #pragma unroll
            for (int nt = 0; nt < 8; nt++) {
                const uint32_t a0 = sb + m0 * ZROWB + ncol + (uint32_t)nt * 32;
                sts64(a0,             acc[mt][nt][0], acc[mt][nt][1]);
                sts64(a0 + 8 * ZROWB, acc[mt][nt][2], acc[mt][nt][3]);
            }
        }
    }
    __syncthreads();

    // ---- epilogue phase 2: gates + cell update, fully coalesced gmem ----
    {
        const int jb   = tid & 7;            // j-block of 4
        const int mrow = tid >> 3;           // 0..31
        const int jcol = (bn >> 2) + jb * 4; // hidden index base (4 consecutive)

        const float4 bi = *(const float4*)(bias + 0 * HID + jcol);
        const float4 bf = *(const float4*)(bias + 1 * HID + jcol);
        const float4 bg = *(const float4*)(bias + 2 * HID + jcol);
        const float4 bo = *(const float4*)(bias + 3 * HID + jcol);
        float4 wi, wf, wg, wo;
        if (colw) {
            wi = *(const float4*)(colw + 0 * HID + jcol);
            wf = *(const float4*)(colw + 1 * HID + jcol);
            wg = *(const float4*)(colw + 2 * HID + jcol);
            wo = *(const float4*)(colw + 3 * HID + jcol);
        }

        #pragma unroll
        for (int mi = 0; mi < 4; mi++) {
            const int m_local = mrow + 32 * mi;
            const int m = bm + m_local;
            const uint32_t zb = sb + (uint32_t)m_local * ZROWB + (uint32_t)jb * 64;
            float4 z0 = lds128(zb);        // j+0: (zi,zf,zg,zo)
            float4 z1 = lds128(zb + 16);   // j+1
            float4 z2 = lds128(zb + 32);   // j+2
            float4 z3 = lds128(zb + 48);   // j+3

            const size_t gidx = (size_t)m * HID + jcol;
            const float4 cp = *(const float4*)(c_prev + gidx);
            const float xv = colw ? rowx[m] : 0.f;

            float zi[4] = {z0.x + bi.x, z1.x + bi.y, z2.x + bi.z, z3.x + bi.w};
            float zf[4] = {z0.y + bf.x, z1.y + bf.y, z2.y + bf.z, z3.y + bf.w};
            float zg[4] = {z0.z + bg.x, z1.z + bg.y, z2.z + bg.z, z3.z + bg.w};
            float zo[4] = {z0.w + bo.x, z1.w + bo.y, z2.w + bo.z, z3.w + bo.w};
            if (colw) {
                zi[0] = fmaf(xv, wi.x, zi[0]); zi[1] = fmaf(xv, wi.y, zi[1]);
                zi[2] = fmaf(xv, wi.z, zi[2]); zi[3] = fmaf(xv, wi.w, zi[3]);
                zf[0] = fmaf(xv, wf.x, zf[0]); zf[1] = fmaf(xv, wf.y, zf[1]);
                zf[2] = fmaf(xv, wf.z, zf[2]); zf[3] = fmaf(xv, wf.w, zf[3]);
                zg[0] = fmaf(xv, wg.x, zg[0]); zg[1] = fmaf(xv, wg.y, zg[1]);
                zg[2] = fmaf(xv, wg.z, zg[2]); zg[3] = fmaf(xv, wg.w, zg[3]);
                zo[0] = fmaf(xv, wo.x, zo[0]); zo[1] = fmaf(xv, wo.y, zo[1]);
                zo[2] = fmaf(xv, wo.z, zo[2]); zo[3] = fmaf(xv, wo.w, zo[3]);
            }
            const float cpv[4] = {cp.x, cp.y, cp.z, cp.w};
            float4 co, ho;
            float* cop = &co.x;
            float* hop = &ho.x;
            __half hv[4];
            #pragma unroll
            for (int q = 0; q < 4; q++) {
                const float ig = 1.f / (1.f + expf(-zi[q]));
                const float fg = 1.f / (1.f + expf(-zf[q]));
                const float gg = tanhf(zg[q]);
                const float og = 1.f / (1.f + expf(-zo[q]));
                const float cc = fmaf(fg, cpv[q], ig * gg);
                const float hh = og * tanhf(cc);
                cop[q] = cc;
                hop[q] = hh;
                hv[q] = __float2half_rn(hh);
            }
            *(float4*)(c_out + gidx) = co;
            *(float4*)(h_out + gidx) = ho;
            *(uint2*)(nA + gidx) = make_uint2(
                (uint32_t)__half_as_ushort(hv[0]) | ((uint32_t)__half_as_ushort(hv[1]) << 16),
                (uint32_t)__half_as_ushort(hv[2]) | ((uint32_t)__half_as_ushort(hv[3]) << 16));
        }
    }
}

// ---------------------------------------------------------------------------
// Weight prep (ALL layers, one launch): transpose, gate-permute, sum, fp16.
// ---------------------------------------------------------------------------
__global__ void wprep(const float* __restrict__ Wh0,
                      const float* __restrict__ Wx, const float* __restrict__ Whh,
                      __half* __restrict__ out)
{
    __shared__ float s[32][33];
    const int l  = blockIdx.z;
    const int k0 = blockIdx.x * 32, n0 = blockIdx.y * 32;
    const int tx = threadIdx.x, ty = threadIdx.y;
    const int n = n0 + tx;
    const int col = (n & 3) * HID + (n >> 2);
    float v;
    if (l == 0) {
        v = Wh0[(size_t)(k0 + ty) * FOURH + col];
    } else {
        const size_t off = (size_t)(l - 1) * HID * FOURH + (size_t)(k0 + ty) * FOURH + col;
        v = Wx[off] + Whh[off];
    }
    s[ty][tx] = v;
    __syncthreads();
    out[(size_t)l * FOURH * HID + (size_t)(n0 + ty) * HID + k0 + tx] =
        __float2half_rn(s[tx][ty]);
}

// ---------------------------------------------------------------------------
// h0 fp32 -> fp16 (vectorized x4)
// ---------------------------------------------------------------------------
__global__ void conv_a(const float* __restrict__ x, __half* __restrict__ o)
{
    const size_t i = (size_t)blockIdx.x * blockDim.x + threadIdx.x;
    float4 v = ((const float4*)x)[i];
    uint32_t p0 = (uint32_t)__half_as_ushort(__float2half_rn(v.x))
                | ((uint32_t)__half_as_ushort(__float2half_rn(v.y)) << 16);
    uint32_t p1 = (uint32_t)__half_as_ushort(__float2half_rn(v.z))
                | ((uint32_t)__half_as_ushort(__float2half_rn(v.w)) << 16);
    ((uint2*)o)[i] = make_uint2(p0, p1);
}

// ---------------------------------------------------------------------------
// Head: pred[b] = dot(h[b,:], Wd) + bd
// ---------------------------------------------------------------------------
__global__ void head_kernel(const float* __restrict__ h, const float* __restrict__ Wd,
                            const float* __restrict__ bd, float* __restrict__ pred, int B)
{
    const int row  = blockIdx.x * (blockDim.x >> 5) + (threadIdx.x >> 5);
    const int lane = threadIdx.x & 31;
    if (row >= B) return;
    const float* hr = h + (size_t)row * HID;
    float s = 0.f;
    #pragma unroll 8
    for (int k = lane; k < HID; k += 32) s = fmaf(hr[k], Wd[k], s);
    #pragma unroll
    for (int off = 16; off; off >>= 1) s += __shfl_down_sync(0xffffffffu, s, off);
    if (lane == 0) pred[row] = s + bd[0];
}

// ---------------------------------------------------------------------------
extern "C" void kernel_launch(void* const* d_in, const int* in_sizes, int n_in,
                              void* d_out, int out_size)
{
    const float* x_todec = (const float*)d_in[0];
    const float* c0      = (const float*)d_in[1];
    const float* h0      = (const float*)d_in[2];
    const float* Wx0     = (const float*)d_in[3];
    const float* Wh0     = (const float*)d_in[4];
    const float* b0      = (const float*)d_in[5];
    const float* Wx      = (const float*)d_in[6];
    const float* Wh      = (const float*)d_in[7];
    const float* bl      = (const float*)d_in[8];
    const float* Wd      = (const float*)d_in[9];
    const float* bd      = (const float*)d_in[10];

    float* out  = (float*)d_out;
    float* cbuf = out;
    float* hbuf = out + (size_t)BATCH * HID;
    float* pred = out + 2 * (size_t)BATCH * HID;

    __half *A0, *A1, *W16;
    cudaGetSymbolAddress((void**)&A0, g_A0);
    cudaGetSymbolAddress((void**)&A1, g_A1);
    cudaGetSymbolAddress((void**)&W16, g_W16);

    static bool attr_set = false;
    if (!attr_set) {
        cudaFuncSetAttribute(gemm_lstm_fused,
                             cudaFuncAttributeMaxDynamicSharedMemorySize, GEMM_SMEM);
        attr_set = true;
    }

    const dim3 ggrid(FOURH / 128, BATCH / 128);   // (32,64)

    wprep<<<dim3(HID / 32, FOURH / 32, NLAYERS), dim3(32, 32)>>>(Wh0, Wx, Wh, W16);
    conv_a<<<(BATCH * HID / 4) / 256, 256>>>(h0, A0);

    __half* cur = A0;
    __half* nxt = A1;

    // layer 0: z = h0 @ Wh0^T (+ x*Wx0 + b0 in epilogue)
    gemm_lstm_fused<<<ggrid, 256, GEMM_SMEM>>>(cur, W16,
                                               b0, x_todec, Wx0,
                                               c0, cbuf, hbuf, nxt);
    // layers 1..3: z = h @ (Wx+Wh)^T + b
    for (int l = 1; l < NLAYERS; l++) {
        __half* t = cur; cur = nxt; nxt = t;
        gemm_lstm_fused<<<ggrid, 256, GEMM_SMEM>>>(cur,
                                                   W16 + (size_t)l * FOURH * HID,
                                                   bl + (size_t)(l - 1) * FOURH,
                                                   nullptr, nullptr,
                                                   cbuf, cbuf, hbuf, nxt);
    }

    head_kernel<<<BATCH / 8, 256>>>(hbuf, Wd, bd, pred, BATCH);
}

// round 12
// speedup vs baseline: 1.3450x; 1.3450x over previous
#include <cuda_runtime.h>
#include <cuda_fp16.h>
#include <cstdint>
#include <math.h>

#define BATCH 8192
#define HID   1024
#define FOURH 4096
#define NLAYERS 4

// ---------------------------------------------------------------------------
// Scratch (allocation-free). Ping-pong activation buffers (cross-CTA safety).
// ---------------------------------------------------------------------------
__device__ __half g_A0[(size_t)BATCH * HID];
__device__ __half g_A1[(size_t)BATCH * HID];
__device__ __half g_W16[(size_t)NLAYERS * FOURH * HID];   // gate-permuted, transposed

// ---------------------------------------------------------------------------
// PTX helpers (arch-agnostic: sm_80+)
// ---------------------------------------------------------------------------
__device__ __forceinline__ uint32_t smem_u32(const void* p) {
    uint32_t a;
    asm("{ .reg .u64 t; cvta.to.shared.u64 t, %1; cvt.u32.u64 %0, t; }" : "=r"(a) : "l"(p));
    return a;
}
__device__ __forceinline__ void cp_async16(uint32_t sdst, const void* gsrc) {
    asm volatile("cp.async.cg.shared.global [%0], [%1], 16;" :: "r"(sdst), "l"(gsrc));
}
__device__ __forceinline__ void cp_commit() { asm volatile("cp.async.commit_group;"); }
template <int N>
__device__ __forceinline__ void cp_wait() { asm volatile("cp.async.wait_group %0;" :: "n"(N)); }

__device__ __forceinline__ void ldm_x4(uint32_t* r, uint32_t addr) {
    asm volatile("ldmatrix.sync.aligned.m8n8.x4.shared.b16 {%0,%1,%2,%3}, [%4];"
                 : "=r"(r[0]), "=r"(r[1]), "=r"(r[2]), "=r"(r[3]) : "r"(addr));
}
// NOTE: no volatile — register-only operands; lets ptxas interleave with LDSM.
__device__ __forceinline__ void mma16816(float* c, const uint32_t* a, const uint32_t* b) {
    asm("mma.sync.aligned.m16n8k16.row.col.f32.f16.f16.f32 "
        "{%0,%1,%2,%3}, {%4,%5,%6,%7}, {%8,%9}, {%0,%1,%2,%3};"
        : "+f"(c[0]), "+f"(c[1]), "+f"(c[2]), "+f"(c[3])
        : "r"(a[0]), "r"(a[1]), "r"(a[2]), "r"(a[3]), "r"(b[0]), "r"(b[1]));
}
__device__ __forceinline__ void sts64(uint32_t addr, float x, float y) {
    asm volatile("st.shared.v2.f32 [%0], {%1, %2};" :: "r"(addr), "f"(x), "f"(y));
}
__device__ __forceinline__ float4 lds128(uint32_t addr) {
    float4 v;
    asm volatile("ld.shared.v4.f32 {%0,%1,%2,%3}, [%4];"
                 : "=f"(v.x), "=f"(v.y), "=f"(v.z), "=f"(v.w) : "r"(addr));
    return v;
}

// ---------------------------------------------------------------------------
// GEMM + fused LSTM gate epilogue + fused next-layer fp16 convert.
// C = A @ W16^T, single fp16 product. CTA tile 128x128, 8 warps (4Mx2N),
// warp tile 32x64. 2 CTAs/SM, 3-stage cp.async pipeline.
// K chunks of 64 fp16, XOR-swizzled 128B rows (c -> c ^ (row&7)).
// ks stagger de-phases SMSP-mates: ks = (kk + wid + ((wid>>2)<<1)) & 3.
// Epilogue stages z in smem (528B row stride) for coalesced gmem I/O.
// ---------------------------------------------------------------------------
#define KC        64
#define NCHUNKS   (HID / KC)               // 16
#define ROWB      128
#define REG_B     (128 * ROWB)             // 16384 B per region
#define STAGE_B   (2 * REG_B)              // 32768 B (A, W)
#define NSTAGES   3
#define ZROWB     528                      // epilogue fp32 row stride
#define GEMM_SMEM (NSTAGES * STAGE_B)      // 98304 B -> 2 CTAs/SM (epilogue needs 67584)

__device__ __forceinline__ void load_region(const __half* g, int row0, int k0,
                                            uint32_t sdst, int tid) {
    const int row  = tid >> 1;
    const int half = tid & 1;
    const __half* src = g + (size_t)(row0 + row) * HID + k0 + half * 32;
    const uint32_t rbase = sdst + (uint32_t)row * ROWB;
    const int rm = row & 7;
    #pragma unroll
    for (int q = 0; q < 4; q++) {
        const int chunk = half * 4 + q;
        cp_async16(rbase + (uint32_t)((chunk ^ rm) << 4), src + q * 8);
    }
}

__global__ __launch_bounds__(256, 2) void gemm_lstm_fused(
    const __half* __restrict__ A,
    const __half* __restrict__ Wh,
    const float* __restrict__ bias,       // [4H] original layout
    const float* __restrict__ rowx,       // [B] or nullptr (layer-0 x)
    const float* __restrict__ colw,       // [4H] or nullptr (layer-0 Wx0)
    const float* __restrict__ c_prev,     // [B,H]
    float* __restrict__ c_out,            // [B,H]
    float* __restrict__ h_out,            // [B,H]
    __half* __restrict__ nA)              // next-layer A (ping-pong buf)
{
    extern __shared__ char smem[];
    const uint32_t sb = smem_u32(smem);

    const int tid    = threadIdx.x;
    const int wid    = tid >> 5;
    const int lane   = tid & 31;
    const int warp_m = wid & 3;
    const int warp_n = wid >> 2;
    const int bm = blockIdx.y * 128;
    const int bn = blockIdx.x * 128;

    const uint32_t swz   = (uint32_t)(lane & 7) << 4;
    const int      arow  = lane & 15;
    const uint32_t acol  = (uint32_t)(lane >> 4) * 16;
    const int      brow  = ((lane >> 4) << 3) | (lane & 7);
    const uint32_t bcol  = (uint32_t)((lane >> 3) & 1) * 16;

    const uint32_t aRowOff = (uint32_t)(warp_m * 32 + arow) * ROWB;
    const uint32_t bRowOff = (uint32_t)(warp_n * 64 + brow) * ROWB;

    // phase offset: warps sharing an SMSP (wid, wid+4) differ by 2
    const int kphase = (wid + ((wid >> 2) << 1)) & 3;

    float acc[2][8][4];
    #pragma unroll
    for (int mt = 0; mt < 2; mt++)
        #pragma unroll
        for (int nt = 0; nt < 8; nt++)
            #pragma unroll
            for (int q = 0; q < 4; q++) acc[mt][nt][q] = 0.f;

    // ---- prologue: fill stages 0..1 ----
    #pragma unroll
    for (int s = 0; s < NSTAGES - 1; s++) {
        const uint32_t sbuf = sb + (uint32_t)s * STAGE_B;
        load_region(A,  bm, s * KC, sbuf, tid);
        load_region(Wh, bn, s * KC, sbuf + REG_B, tid);
        cp_commit();
    }

    int stage_c = 0;        // stage index of chunk c
    int stage_p = NSTAGES - 1;  // stage index for prefetched chunk
    for (int c = 0; c < NCHUNKS; ++c) {
        if (c + NSTAGES - 1 < NCHUNKS) {
            const uint32_t sbuf = sb + (uint32_t)stage_p * STAGE_B;
            load_region(A,  bm, (c + NSTAGES - 1) * KC, sbuf, tid);
            load_region(Wh, bn, (c + NSTAGES - 1) * KC, sbuf + REG_B, tid);
        }
        cp_commit();                   // empty group when no loads: uniform accounting
        cp_wait<NSTAGES - 1>();        // stage for chunk c complete
        __syncthreads();

        const uint32_t base  = sb + (uint32_t)stage_c * STAGE_B;
        const uint32_t aBase = base + aRowOff;
        const uint32_t bBase = base + REG_B + bRowOff;

        #pragma unroll
        for (int kk = 0; kk < 4; kk++) {
            const int ks = (kk + kphase) & 3;               // de-phase SMSP-mates
            const uint32_t ko = (uint32_t)ks * 32;          // 16 fp16 = 32 B
            const uint32_t aOff = (acol + ko) ^ swz;
            const uint32_t bOff = (bcol + ko) ^ swz;

            uint32_t ah[2][4], bh[4][4];
            #pragma unroll
            for (int np = 0; np < 4; np++)
                ldm_x4(bh[np], bBase + (uint32_t)np * 16 * ROWB + bOff);
            #pragma unroll
            for (int mt = 0; mt < 2; mt++)
                ldm_x4(ah[mt], aBase + (uint32_t)mt * 16 * ROWB + aOff);

            #pragma unroll
            for (int mt = 0; mt < 2; mt++)
                #pragma unroll
                for (int nt = 0; nt < 8; nt++)
                    mma16816(acc[mt][nt], ah[mt], &bh[nt >> 1][(nt & 1) * 2]);
        }
        __syncthreads();               // all reads of this stage done before reuse

        stage_c = (stage_c + 1 == NSTAGES) ? 0 : stage_c + 1;
        stage_p = (stage_p + 1 == NSTAGES) ? 0 : stage_p + 1;
    }

    // ---- epilogue phase 1: stage z tile to smem (row stride 528B) ----
    {
        const int quad = lane >> 2;
        const uint32_t ncol = (uint32_t)(warp_n * 64 + 2 * (lane & 3)) * 4;
        #pragma unroll
        for (int mt = 0; mt < 2; mt++) {
            const uint32_t m0 = (uint32_t)(warp_m * 32 + mt * 16 + quad);
            #pragma unroll
            for (int nt = 0; nt < 8; nt++) {
                const uint32_t a0 = sb + m0 * ZROWB + ncol + (uint32_t)nt * 32;
                sts64(a0,             acc[mt][nt][0], acc[mt][nt][1]);
                sts64(a0 + 8 * ZROWB, acc[mt][nt][2], acc[mt][nt][3]);
            }
        }
    }
    __syncthreads();

    // ---- epilogue phase 2: gates + cell update, fully coalesced gmem ----
    {
        const int jb   = tid & 7;            // j-block of 4
        const int mrow = tid >> 3;           // 0..31
        const int jcol = (bn >> 2) + jb * 4; // hidden index base (4 consecutive)

        const float4 bi = *(const float4*)(bias + 0 * HID + jcol);
        const float4 bf = *(const float4*)(bias + 1 * HID + jcol);
        const float4 bg = *(const float4*)(bias + 2 * HID + jcol);
        const float4 bo = *(const float4*)(bias + 3 * HID + jcol);
        float4 wi, wf, wg, wo;
        if (colw) {
            wi = *(const float4*)(colw + 0 * HID + jcol);
            wf = *(const float4*)(colw + 1 * HID + jcol);
            wg = *(const float4*)(colw + 2 * HID + jcol);
            wo = *(const float4*)(colw + 3 * HID + jcol);
        }

        #pragma unroll
        for (int mi = 0; mi < 4; mi++) {
            const int m_local = mrow + 32 * mi;
            const int m = bm + m_local;
            const uint32_t zb = sb + (uint32_t)m_local * ZROWB + (uint32_t)jb * 64;
            float4 z0 = lds128(zb);        // j+0: (zi,zf,zg,zo)
            float4 z1 = lds128(zb + 16);   // j+1
            float4 z2 = lds128(zb + 32);   // j+2
            float4 z3 = lds128(zb + 48);   // j+3

            const size_t gidx = (size_t)m * HID + jcol;
            const float4 cp = *(const float4*)(c_prev + gidx);
            const float xv = colw ? rowx[m] : 0.f;

            float zi[4] = {z0.x + bi.x, z1.x + bi.y, z2.x + bi.z, z3.x + bi.w};
            float zf[4] = {z0.y + bf.x, z1.y + bf.y, z2.y + bf.z, z3.y + bf.w};
            float zg[4] = {z0.z + bg.x, z1.z + bg.y, z2.z + bg.z, z3.z + bg.w};
            float zo[4] = {z0.w + bo.x, z1.w + bo.y, z2.w + bo.z, z3.w + bo.w};
            if (colw) {
                zi[0] = fmaf(xv, wi.x, zi[0]); zi[1] = fmaf(xv, wi.y, zi[1]);
                zi[2] = fmaf(xv, wi.z, zi[2]); zi[3] = fmaf(xv, wi.w, zi[3]);
                zf[0] = fmaf(xv, wf.x, zf[0]); zf[1] = fmaf(xv, wf.y, zf[1]);
                zf[2] = fmaf(xv, wf.z, zf[2]); zf[3] = fmaf(xv, wf.w, zf[3]);
                zg[0] = fmaf(xv, wg.x, zg[0]); zg[1] = fmaf(xv, wg.y, zg[1]);
                zg[2] = fmaf(xv, wg.z, zg[2]); zg[3] = fmaf(xv, wg.w, zg[3]);
                zo[0] = fmaf(xv, wo.x, zo[0]); zo[1] = fmaf(xv, wo.y, zo[1]);
                zo[2] = fmaf(xv, wo.z, zo[2]); zo[3] = fmaf(xv, wo.w, zo[3]);
            }
            const float cpv[4] = {cp.x, cp.y, cp.z, cp.w};
            float4 co, ho;
            float* cop = &co.x;
            float* hop = &ho.x;
            __half hv[4];
            #pragma unroll
            for (int q = 0; q < 4; q++) {
                const float ig = 1.f / (1.f + expf(-zi[q]));
                const float fg = 1.f / (1.f + expf(-zf[q]));
                const float gg = tanhf(zg[q]);
                const float og = 1.f / (1.f + expf(-zo[q]));
                const float cc = fmaf(fg, cpv[q], ig * gg);
                const float hh = og * tanhf(cc);
                cop[q] = cc;
                hop[q] = hh;
                hv[q] = __float2half_rn(hh);
            }
            *(float4*)(c_out + gidx) = co;
            *(float4*)(h_out + gidx) = ho;
            *(uint2*)(nA + gidx) = make_uint2(
                (uint32_t)__half_as_ushort(hv[0]) | ((uint32_t)__half_as_ushort(hv[1]) << 16),
                (uint32_t)__half_as_ushort(hv[2]) | ((uint32_t)__half_as_ushort(hv[3]) << 16));
        }
    }
}

// ---------------------------------------------------------------------------
// Weight prep (ALL layers, one launch): transpose, gate-permute, sum, fp16.
// ---------------------------------------------------------------------------
__global__ void wprep(const float* __restrict__ Wh0,
                      const float* __restrict__ Wx, const float* __restrict__ Whh,
                      __half* __restrict__ out)
{
    __shared__ float s[32][33];
    const int l  = blockIdx.z;
    const int k0 = blockIdx.x * 32, n0 = blockIdx.y * 32;
    const int tx = threadIdx.x, ty = threadIdx.y;
    const int n = n0 + tx;
    const int col = (n & 3) * HID + (n >> 2);
    float v;
    if (l == 0) {
        v = Wh0[(size_t)(k0 + ty) * FOURH + col];
    } else {
        const size_t off = (size_t)(l - 1) * HID * FOURH + (size_t)(k0 + ty) * FOURH + col;
        v = Wx[off] + Whh[off];
    }
    s[ty][tx] = v;
    __syncthreads();
    out[(size_t)l * FOURH * HID + (size_t)(n0 + ty) * HID + k0 + tx] =
        __float2half_rn(s[tx][ty]);
}

// ---------------------------------------------------------------------------
// h0 fp32 -> fp16 (vectorized x4)
// ---------------------------------------------------------------------------
__global__ void conv_a(const float* __restrict__ x, __half* __restrict__ o)
{
    const size_t i = (size_t)blockIdx.x * blockDim.x + threadIdx.x;
    float4 v = ((const float4*)x)[i];
    uint32_t p0 = (uint32_t)__half_as_ushort(__float2half_rn(v.x))
                | ((uint32_t)__half_as_ushort(__float2half_rn(v.y)) << 16);
    uint32_t p1 = (uint32_t)__half_as_ushort(__float2half_rn(v.z))
                | ((uint32_t)__half_as_ushort(__float2half_rn(v.w)) << 16);
    ((uint2*)o)[i] = make_uint2(p0, p1);
}

// ---------------------------------------------------------------------------
// Head: pred[b] = dot(h[b,:], Wd) + bd
// ---------------------------------------------------------------------------
__global__ void head_kernel(const float* __restrict__ h, const float* __restrict__ Wd,
                            const float* __restrict__ bd, float* __restrict__ pred, int B)
{
    const int row  = blockIdx.x * (blockDim.x >> 5) + (threadIdx.x >> 5);
    const int lane = threadIdx.x & 31;
    if (row >= B) return;
    const float* hr = h + (size_t)row * HID;
    float s = 0.f;
    #pragma unroll 8
    for (int k = lane; k < HID; k += 32) s = fmaf(hr[k], Wd[k], s);
    #pragma unroll
    for (int off = 16; off; off >>= 1) s += __shfl_down_sync(0xffffffffu, s, off);
    if (lane == 0) pred[row] = s + bd[0];
}

// ---------------------------------------------------------------------------
extern "C" void kernel_launch(void* const* d_in, const int* in_sizes, int n_in,
                              void* d_out, int out_size)
{
    const float* x_todec = (const float*)d_in[0];
    const float* c0      = (const float*)d_in[1];
    const float* h0      = (const float*)d_in[2];
    const float* Wx0     = (const float*)d_in[3];
    const float* Wh0     = (const float*)d_in[4];
    const float* b0      = (const float*)d_in[5];
    const float* Wx      = (const float*)d_in[6];
    const float* Wh      = (const float*)d_in[7];
    const float* bl      = (const float*)d_in[8];
    const float* Wd      = (const float*)d_in[9];
    const float* bd      = (const float*)d_in[10];

    float* out  = (float*)d_out;
    float* cbuf = out;
    float* hbuf = out + (size_t)BATCH * HID;
    float* pred = out + 2 * (size_t)BATCH * HID;

    __half *A0, *A1, *W16;
    cudaGetSymbolAddress((void**)&A0, g_A0);
    cudaGetSymbolAddress((void**)&A1, g_A1);
    cudaGetSymbolAddress((void**)&W16, g_W16);

    static bool attr_set = false;
    if (!attr_set) {
        cudaFuncSetAttribute(gemm_lstm_fused,
                             cudaFuncAttributeMaxDynamicSharedMemorySize, GEMM_SMEM);
        attr_set = true;
    }

    const dim3 ggrid(FOURH / 128, BATCH / 128);   // (32,64)

    wprep<<<dim3(HID / 32, FOURH / 32, NLAYERS), dim3(32, 32)>>>(Wh0, Wx, Wh, W16);
    conv_a<<<(BATCH * HID / 4) / 256, 256>>>(h0, A0);

    __half* cur = A0;
    __half* nxt = A1;

    // layer 0: z = h0 @ Wh0^T (+ x*Wx0 + b0 in epilogue)
    gemm_lstm_fused<<<ggrid, 256, GEMM_SMEM>>>(cur, W16,
                                               b0, x_todec, Wx0,
                                               c0, cbuf, hbuf, nxt);
    // layers 1..3: z = h @ (Wx+Wh)^T + b
    for (int l = 1; l < NLAYERS; l++) {
        __half* t = cur; cur = nxt; nxt = t;
        gemm_lstm_fused<<<ggrid, 256, GEMM_SMEM>>>(cur,
                                                   W16 + (size_t)l * FOURH * HID,
                                                   bl + (size_t)(l - 1) * FOURH,
                                                   nullptr, nullptr,
                                                   cbuf, cbuf, hbuf, nxt);
    }

    head_kernel<<<BATCH / 8, 256>>>(hbuf, Wd, bd, pred, BATCH);
}

// round 13
// speedup vs baseline: 1.4052x; 1.0448x over previous
#include <cuda_runtime.h>
#include <cuda_fp16.h>
#include <cstdint>
#include <math.h>

#define BATCH 8192
#define HID   1024
#define FOURH 4096
#define NLAYERS 4

// ---------------------------------------------------------------------------
// Scratch (allocation-free). Ping-pong activation buffers (cross-CTA safety).
// ---------------------------------------------------------------------------
__device__ __half g_A0[(size_t)BATCH * HID];
__device__ __half g_A1[(size_t)BATCH * HID];
__device__ __half g_W16[(size_t)NLAYERS * FOURH * HID];   // gate-permuted, transposed

// ---------------------------------------------------------------------------
// PTX helpers (arch-agnostic: sm_80+)
// ---------------------------------------------------------------------------
__device__ __forceinline__ uint32_t smem_u32(const void* p) {
    uint32_t a;
    asm("{ .reg .u64 t; cvta.to.shared.u64 t, %1; cvt.u32.u64 %0, t; }" : "=r"(a) : "l"(p));
    return a;
}
__device__ __forceinline__ void cp_async16(uint32_t sdst, const void* gsrc) {
    asm volatile("cp.async.cg.shared.global [%0], [%1], 16;" :: "r"(sdst), "l"(gsrc));
}
__device__ __forceinline__ void cp_commit() { asm volatile("cp.async.commit_group;"); }
template <int N>
__device__ __forceinline__ void cp_wait() { asm volatile("cp.async.wait_group %0;" :: "n"(N)); }

__device__ __forceinline__ void ldm_x4(uint32_t* r, uint32_t addr) {
    asm volatile("ldmatrix.sync.aligned.m8n8.x4.shared.b16 {%0,%1,%2,%3}, [%4];"
                 : "=r"(r[0]), "=r"(r[1]), "=r"(r[2]), "=r"(r[3]) : "r"(addr));
}
__device__ __forceinline__ void mma16816(float* c, const uint32_t* a, const uint32_t* b) {
    asm("mma.sync.aligned.m16n8k16.row.col.f32.f16.f16.f32 "
        "{%0,%1,%2,%3}, {%4,%5,%6,%7}, {%8,%9}, {%0,%1,%2,%3};"
        : "+f"(c[0]), "+f"(c[1]), "+f"(c[2]), "+f"(c[3])
        : "r"(a[0]), "r"(a[1]), "r"(a[2]), "r"(a[3]), "r"(b[0]), "r"(b[1]));
}
__device__ __forceinline__ void sts64(uint32_t addr, float x, float y) {
    asm volatile("st.shared.v2.f32 [%0], {%1, %2};" :: "r"(addr), "f"(x), "f"(y));
}
__device__ __forceinline__ float4 lds128(uint32_t addr) {
    float4 v;
    asm volatile("ld.shared.v4.f32 {%0,%1,%2,%3}, [%4];"
                 : "=f"(v.x), "=f"(v.y), "=f"(v.z), "=f"(v.w) : "r"(addr));
    return v;
}

// Fast transcendentals (bounded args; error ~1e-7 — negligible vs 2.6e-4 budget)
__device__ __forceinline__ float fsigmoid(float z) {
    return __fdividef(1.f, 1.f + __expf(-z));
}
__device__ __forceinline__ float ftanh(float x) {
    const float t = __expf(-2.f * x);
    return __fdividef(1.f - t, 1.f + t);
}

// ---------------------------------------------------------------------------
// GEMM + fused LSTM gate epilogue + fused next-layer fp16 convert.
// C = A @ W16^T, single fp16 product. CTA tile 128x128, 8 warps (4Mx2N),
// warp tile 32x64. 2 CTAs/SM, double-buffered K chunks of 64 fp16,
// XOR-swizzled 128B rows (c -> c ^ (row&7)).
// Epilogue stages z in smem (528B row stride) for coalesced gmem I/O.
// ---------------------------------------------------------------------------
#define KC        64
#define NCHUNKS   (HID / KC)               // 16
#define ROWB      128
#define REG_B     (128 * ROWB)             // 16384 B per region
#define STAGE_B   (2 * REG_B)              // 32768 B (A, W)
#define ZROWB     528                      // epilogue fp32 row stride
#define GEMM_SMEM (128 * ZROWB)            // 67584 B (mainloop uses 65536)

__device__ __forceinline__ void load_region(const __half* g, int row0, int k0,
                                            uint32_t sdst, int tid) {
    const int row  = tid >> 1;
    const int half = tid & 1;
    const __half* src = g + (size_t)(row0 + row) * HID + k0 + half * 32;
    const uint32_t rbase = sdst + (uint32_t)row * ROWB;
    const int rm = row & 7;
    #pragma unroll
    for (int q = 0; q < 4; q++) {
        const int chunk = half * 4 + q;
        cp_async16(rbase + (uint32_t)((chunk ^ rm) << 4), src + q * 8);
    }
}

__global__ __launch_bounds__(256, 2) void gemm_lstm_fused(
    const __half* __restrict__ A,
    const __half* __restrict__ Wh,
    const float* __restrict__ bias,       // [4H] original layout
    const float* __restrict__ rowx,       // [B] or nullptr (layer-0 x)
    const float* __restrict__ colw,       // [4H] or nullptr (layer-0 Wx0)
    const float* __restrict__ c_prev,     // [B,H]
    float* __restrict__ c_out,            // [B,H]
    float* __restrict__ h_out,            // [B,H]
    __half* __restrict__ nA)              // next-layer A (ping-pong buf)
{
    extern __shared__ char smem[];
    const uint32_t sb = smem_u32(smem);

    const int tid    = threadIdx.x;
    const int wid    = tid >> 5;
    const int lane   = tid & 31;
    const int warp_m = wid & 3;
    const int warp_n = wid >> 2;
    const int bm = blockIdx.y * 128;
    const int bn = blockIdx.x * 128;

    const uint32_t swz   = (uint32_t)(lane & 7) << 4;
    const int      arow  = lane & 15;
    const uint32_t acol  = (uint32_t)(lane >> 4) * 16;
    const int      brow  = ((lane >> 4) << 3) | (lane & 7);
    const uint32_t bcol  = (uint32_t)((lane >> 3) & 1) * 16;

    const uint32_t aRowOff = (uint32_t)(warp_m * 32 + arow) * ROWB;
    const uint32_t bRowOff = (uint32_t)(warp_n * 64 + brow) * ROWB;

    float acc[2][8][4];
    #pragma unroll
    for (int mt = 0; mt < 2; mt++)
        #pragma unroll
        for (int nt = 0; nt < 8; nt++)
            #pragma unroll
            for (int q = 0; q < 4; q++) acc[mt][nt][q] = 0.f;

    load_region(A,  bm, 0, sb + 0 * REG_B, tid);
    load_region(Wh, bn, 0, sb + 1 * REG_B, tid);
    cp_commit();

    for (int c = 0; c < NCHUNKS; ++c) {
        if (c + 1 < NCHUNKS) {
            const uint32_t sbuf = sb + ((c + 1) & 1) * STAGE_B;
            const int k0 = (c + 1) * KC;
            load_region(A,  bm, k0, sbuf, tid);
            load_region(Wh, bn, k0, sbuf + REG_B, tid);
            cp_commit();
            cp_wait<1>();
        } else {
            cp_wait<0>();
        }
        __syncthreads();

        const uint32_t base  = sb + (c & 1) * STAGE_B;
        const uint32_t aBase = base + aRowOff;
        const uint32_t bBase = base + REG_B + bRowOff;

        #pragma unroll
        for (int kk = 0; kk < 4; kk++) {
            const int ks = (kk + wid) & 3;
            const uint32_t ko = (uint32_t)ks * 32;          // 16 fp16 = 32 B
            const uint32_t aOff = (acol + ko) ^ swz;
            const uint32_t bOff = (bcol + ko) ^ swz;

            uint32_t ah[2][4], bh[4][4];
            #pragma unroll
            for (int np = 0; np < 4; np++)
                ldm_x4(bh[np], bBase + (uint32_t)np * 16 * ROWB + bOff);
            #pragma unroll
            for (int mt = 0; mt < 2; mt++)
                ldm_x4(ah[mt], aBase + (uint32_t)mt * 16 * ROWB + aOff);

            #pragma unroll
            for (int mt = 0; mt < 2; mt++)
                #pragma unroll
                for (int nt = 0; nt < 8; nt++)
                    mma16816(acc[mt][nt], ah[mt], &bh[nt >> 1][(nt & 1) * 2]);
        }
        __syncthreads();
    }

    // ---- epilogue phase 1: stage z tile to smem (row stride 528B) ----
    {
        const int quad = lane >> 2;
        const uint32_t ncol = (uint32_t)(warp_n * 64 + 2 * (lane & 3)) * 4;
        #pragma unroll
        for (int mt = 0; mt < 2; mt++) {
            const uint32_t m0 = (uint32_t)(warp_m * 32 + mt * 16 + quad);
            #pragma unroll
            for (int nt = 0; nt < 8; nt++) {
                const uint32_t a0 = sb + m0 * ZROWB + ncol + (uint32_t)nt * 32;
                sts64(a0,             acc[mt][nt][0], acc[mt][nt][1]);
                sts64(a0 + 8 * ZROWB, acc[mt][nt][2], acc[mt][nt][3]);
            }
        }
    }
    __syncthreads();

    // ---- epilogue phase 2: gates + cell update, fully coalesced gmem ----
    {
        const int jb   = tid & 7;            // j-block of 4
        const int mrow = tid >> 3;           // 0..31
        const int jcol = (bn >> 2) + jb * 4; // hidden index base (4 consecutive)

        const float4 bi = *(const float4*)(bias + 0 * HID + jcol);
        const float4 bf = *(const float4*)(bias + 1 * HID + jcol);
        const float4 bg = *(const float4*)(bias + 2 * HID + jcol);
        const float4 bo = *(const float4*)(bias + 3 * HID + jcol);
        float4 wi, wf, wg, wo;
        if (colw) {
            wi = *(const float4*)(colw + 0 * HID + jcol);
            wf = *(const float4*)(colw + 1 * HID + jcol);
            wg = *(const float4*)(colw + 2 * HID + jcol);
            wo = *(const float4*)(colw + 3 * HID + jcol);
        }

        #pragma unroll
        for (int mi = 0; mi < 4; mi++) {
            const int m_local = mrow + 32 * mi;
            const int m = bm + m_local;
            const uint32_t zb = sb + (uint32_t)m_local * ZROWB + (uint32_t)jb * 64;
            float4 z0 = lds128(zb);        // j+0: (zi,zf,zg,zo)
            float4 z1 = lds128(zb + 16);   // j+1
            float4 z2 = lds128(zb + 32);   // j+2
            float4 z3 = lds128(zb + 48);   // j+3

            const size_t gidx = (size_t)m * HID + jcol;
            const float4 cp = *(const float4*)(c_prev + gidx);
            const float xv = colw ? rowx[m] : 0.f;

            float zi[4] = {z0.x + bi.x, z1.x + bi.y, z2.x + bi.z, z3.x + bi.w};
            float zf[4] = {z0.y + bf.x, z1.y + bf.y, z2.y + bf.z, z3.y + bf.w};
            float zg[4] = {z0.z + bg.x, z1.z + bg.y, z2.z + bg.z, z3.z + bg.w};
            float zo[4] = {z0.w + bo.x, z1.w + bo.y, z2.w + bo.z, z3.w + bo.w};
            if (colw) {
                zi[0] = fmaf(xv, wi.x, zi[0]); zi[1] = fmaf(xv, wi.y, zi[1]);
                zi[2] = fmaf(xv, wi.z, zi[2]); zi[3] = fmaf(xv, wi.w, zi[3]);
                zf[0] = fmaf(xv, wf.x, zf[0]); zf[1] = fmaf(xv, wf.y, zf[1]);
                zf[2] = fmaf(xv, wf.z, zf[2]); zf[3] = fmaf(xv, wf.w, zf[3]);
                zg[0] = fmaf(xv, wg.x, zg[0]); zg[1] = fmaf(xv, wg.y, zg[1]);
                zg[2] = fmaf(xv, wg.z, zg[2]); zg[3] = fmaf(xv, wg.w, zg[3]);
                zo[0] = fmaf(xv, wo.x, zo[0]); zo[1] = fmaf(xv, wo.y, zo[1]);
                zo[2] = fmaf(xv, wo.z, zo[2]); zo[3] = fmaf(xv, wo.w, zo[3]);
            }
            const float cpv[4] = {cp.x, cp.y, cp.z, cp.w};
            float4 co, ho;
            float* cop = &co.x;
            float* hop = &ho.x;
            __half hv[4];
            #pragma unroll
            for (int q = 0; q < 4; q++) {
                const float ig = fsigmoid(zi[q]);
                const float fg = fsigmoid(zf[q]);
                const float gg = ftanh(zg[q]);
                const float og = fsigmoid(zo[q]);
                const float cc = fmaf(fg, cpv[q], ig * gg);
                const float hh = og * ftanh(cc);
                cop[q] = cc;
                hop[q] = hh;
                hv[q] = __float2half_rn(hh);
            }
            *(float4*)(c_out + gidx) = co;
            *(float4*)(h_out + gidx) = ho;
            *(uint2*)(nA + gidx) = make_uint2(
                (uint32_t)__half_as_ushort(hv[0]) | ((uint32_t)__half_as_ushort(hv[1]) << 16),
                (uint32_t)__half_as_ushort(hv[2]) | ((uint32_t)__half_as_ushort(hv[3]) << 16));
        }
    }
}

// ---------------------------------------------------------------------------
// Weight prep (ALL layers, one launch), COALESCED both ways:
// read W[k][c] with c consecutive (128B/warp-row), smem transpose, write
// out[n][k] with k consecutive (64B/warp-row), where n = 4*(c&1023)+(c>>10).
// ---------------------------------------------------------------------------
__global__ void wprep(const float* __restrict__ Wh0,
                      const float* __restrict__ Wx, const float* __restrict__ Whh,
                      __half* __restrict__ out)
{
    __shared__ float s[32][33];
    const int l  = blockIdx.z;
    const int k0 = blockIdx.x * 32;
    const int c0 = blockIdx.y * 32;
    const int tx = threadIdx.x, ty = threadIdx.y;

    float v;
    if (l == 0) {
        v = Wh0[(size_t)(k0 + ty) * FOURH + c0 + tx];
    } else {
        const size_t off = (size_t)(l - 1) * HID * FOURH + (size_t)(k0 + ty) * FOURH + c0 + tx;
        v = Wx[off] + Whh[off];
    }
    s[ty][tx] = v;
    __syncthreads();

    // output row n for column c = c0 + ty  (c0 32-aligned: no 1024-block wrap)
    const int n = 4 * ((c0 & (HID - 1)) + ty) + (c0 >> 10);
    out[(size_t)l * FOURH * HID + (size_t)n * HID + k0 + tx] =
        __float2half_rn(s[tx][ty]);
}

// ---------------------------------------------------------------------------
// h0 fp32 -> fp16 (vectorized x4)
// ---------------------------------------------------------------------------
__global__ void conv_a(const float* __restrict__ x, __half* __restrict__ o)
{
    const size_t i = (size_t)blockIdx.x * blockDim.x + threadIdx.x;
    float4 v = ((const float4*)x)[i];
    uint32_t p0 = (uint32_t)__half_as_ushort(__float2half_rn(v.x))
                | ((uint32_t)__half_as_ushort(__float2half_rn(v.y)) << 16);
    uint32_t p1 = (uint32_t)__half_as_ushort(__float2half_rn(v.z))
                | ((uint32_t)__half_as_ushort(__float2half_rn(v.w)) << 16);
    ((uint2*)o)[i] = make_uint2(p0, p1);
}

// ---------------------------------------------------------------------------
// Head: pred[b] = dot(h[b,:], Wd) + bd
// ---------------------------------------------------------------------------
__global__ void head_kernel(const float* __restrict__ h, const float* __restrict__ Wd,
                            const float* __restrict__ bd, float* __restrict__ pred, int B)
{
    const int row  = blockIdx.x * (blockDim.x >> 5) + (threadIdx.x >> 5);
    const int lane = threadIdx.x & 31;
    if (row >= B) return;
    const float* hr = h + (size_t)row * HID;
    float s = 0.f;
    #pragma unroll 8
    for (int k = lane; k < HID; k += 32) s = fmaf(hr[k], Wd[k], s);
    #pragma unroll
    for (int off = 16; off; off >>= 1) s += __shfl_down_sync(0xffffffffu, s, off);
    if (lane == 0) pred[row] = s + bd[0];
}

// ---------------------------------------------------------------------------
extern "C" void kernel_launch(void* const* d_in, const int* in_sizes, int n_in,
                              void* d_out, int out_size)
{
    const float* x_todec = (const float*)d_in[0];
    const float* c0      = (const float*)d_in[1];
    const float* h0      = (const float*)d_in[2];
    const float* Wx0     = (const float*)d_in[3];
    const float* Wh0     = (const float*)d_in[4];
    const float* b0      = (const float*)d_in[5];
    const float* Wx      = (const float*)d_in[6];
    const float* Wh      = (const float*)d_in[7];
    const float* bl      = (const float*)d_in[8];
    const float* Wd      = (const float*)d_in[9];
    const float* bd      = (const float*)d_in[10];

    float* out  = (float*)d_out;
    float* cbuf = out;
    float* hbuf = out + (size_t)BATCH * HID;
    float* pred = out + 2 * (size_t)BATCH * HID;

    __half *A0, *A1, *W16;
    cudaGetSymbolAddress((void**)&A0, g_A0);
    cudaGetSymbolAddress((void**)&A1, g_A1);
    cudaGetSymbolAddress((void**)&W16, g_W16);

    static bool attr_set = false;
    if (!attr_set) {
        cudaFuncSetAttribute(gemm_lstm_fused,
                             cudaFuncAttributeMaxDynamicSharedMemorySize, GEMM_SMEM);
        attr_set = true;
    }

    const dim3 ggrid(FOURH / 128, BATCH / 128);   // (32,64)

    wprep<<<dim3(HID / 32, FOURH / 32, NLAYERS), dim3(32, 32)>>>(Wh0, Wx, Wh, W16);
    conv_a<<<(BATCH * HID / 4) / 256, 256>>>(h0, A0);

    __half* cur = A0;
    __half* nxt = A1;

    // layer 0: z = h0 @ Wh0^T (+ x*Wx0 + b0 in epilogue)
    gemm_lstm_fused<<<ggrid, 256, GEMM_SMEM>>>(cur, W16,
                                               b0, x_todec, Wx0,
                                               c0, cbuf, hbuf, nxt);
    // layers 1..3: z = h @ (Wx+Wh)^T + b
    for (int l = 1; l < NLAYERS; l++) {
        __half* t = cur; cur = nxt; nxt = t;
        gemm_lstm_fused<<<ggrid, 256, GEMM_SMEM>>>(cur,
                                                   W16 + (size_t)l * FOURH * HID,
                                                   bl + (size_t)(l - 1) * FOURH,
                                                   nullptr, nullptr,
                                                   cbuf, cbuf, hbuf, nxt);
    }

    head_kernel<<<BATCH / 8, 256>>>(hbuf, Wd, bd, pred, BATCH);
}

// round 14
// speedup vs baseline: 1.4194x; 1.0102x over previous
#include <cuda_runtime.h>
#include <cuda_fp16.h>
#include <cstdint>
#include <math.h>

#define BATCH 8192
#define HID   1024
#define FOURH 4096
#define NLAYERS 4

// ---------------------------------------------------------------------------
// Scratch (allocation-free). Ping-pong activation buffers (cross-CTA safety).
// ---------------------------------------------------------------------------
__device__ __half g_A0[(size_t)BATCH * HID];
__device__ __half g_A1[(size_t)BATCH * HID];
__device__ __half g_W16[(size_t)NLAYERS * FOURH * HID];   // gate-permuted, transposed

// ---------------------------------------------------------------------------
// PTX helpers (arch-agnostic: sm_80+)
// ---------------------------------------------------------------------------
__device__ __forceinline__ uint32_t smem_u32(const void* p) {
    uint32_t a;
    asm("{ .reg .u64 t; cvta.to.shared.u64 t, %1; cvt.u32.u64 %0, t; }" : "=r"(a) : "l"(p));
    return a;
}
__device__ __forceinline__ void cp_async16(uint32_t sdst, const void* gsrc) {
    asm volatile("cp.async.cg.shared.global [%0], [%1], 16;" :: "r"(sdst), "l"(gsrc));
}
__device__ __forceinline__ void cp_commit() { asm volatile("cp.async.commit_group;"); }
template <int N>
__device__ __forceinline__ void cp_wait() { asm volatile("cp.async.wait_group %0;" :: "n"(N)); }

__device__ __forceinline__ void ldm_x4(uint32_t* r, uint32_t addr) {
    asm volatile("ldmatrix.sync.aligned.m8n8.x4.shared.b16 {%0,%1,%2,%3}, [%4];"
                 : "=r"(r[0]), "=r"(r[1]), "=r"(r[2]), "=r"(r[3]) : "r"(addr));
}
__device__ __forceinline__ void mma16816(float* c, const uint32_t* a, const uint32_t* b) {
    asm("mma.sync.aligned.m16n8k16.row.col.f32.f16.f16.f32 "
        "{%0,%1,%2,%3}, {%4,%5,%6,%7}, {%8,%9}, {%0,%1,%2,%3};"
        : "+f"(c[0]), "+f"(c[1]), "+f"(c[2]), "+f"(c[3])
        : "r"(a[0]), "r"(a[1]), "r"(a[2]), "r"(a[3]), "r"(b[0]), "r"(b[1]));
}
__device__ __forceinline__ void sts64(uint32_t addr, float x, float y) {
    asm volatile("st.shared.v2.f32 [%0], {%1, %2};" :: "r"(addr), "f"(x), "f"(y));
}
__device__ __forceinline__ float4 lds128(uint32_t addr) {
    float4 v;
    asm volatile("ld.shared.v4.f32 {%0,%1,%2,%3}, [%4];"
                 : "=f"(v.x), "=f"(v.y), "=f"(v.z), "=f"(v.w) : "r"(addr));
    return v;
}

// Fast transcendentals (bounded args; error ~1e-7 — negligible vs 2.6e-4 budget)
__device__ __forceinline__ float fsigmoid(float z) {
    return __fdividef(1.f, 1.f + __expf(-z));
}
__device__ __forceinline__ float ftanh(float x) {
    const float t = __expf(-2.f * x);
    return __fdividef(1.f - t, 1.f + t);
}

// ---------------------------------------------------------------------------
// GEMM + fused LSTM gate epilogue + fused next-layer fp16 convert
// + (last layer) fused prediction head via atomicAdd partials.
// C = A @ W16^T, single fp16 product. CTA tile 128x128, 8 warps (4Mx2N),
// warp tile 32x64. 2 CTAs/SM, double-buffered K chunks of 64 fp16,
// XOR-swizzled 128B rows (c -> c ^ (row&7)).
// Epilogue stages z in smem (528B row stride) for coalesced gmem I/O.
// ---------------------------------------------------------------------------
#define KC        64
#define NCHUNKS   (HID / KC)               // 16
#define ROWB      128
#define REG_B     (128 * ROWB)             // 16384 B per region
#define STAGE_B   (2 * REG_B)              // 32768 B (A, W)
#define ZROWB     528                      // epilogue fp32 row stride
#define GEMM_SMEM (128 * ZROWB)            // 67584 B (mainloop uses 65536)

__device__ __forceinline__ void load_region(const __half* g, int row0, int k0,
                                            uint32_t sdst, int tid) {
    const int row  = tid >> 1;
    const int half = tid & 1;
    const __half* src = g + (size_t)(row0 + row) * HID + k0 + half * 32;
    const uint32_t rbase = sdst + (uint32_t)row * ROWB;
    const int rm = row & 7;
    #pragma unroll
    for (int q = 0; q < 4; q++) {
        const int chunk = half * 4 + q;
        cp_async16(rbase + (uint32_t)((chunk ^ rm) << 4), src + q * 8);
    }
}

__global__ __launch_bounds__(256, 2) void gemm_lstm_fused(
    const __half* __restrict__ A,
    const __half* __restrict__ Wh,
    const float* __restrict__ bias,       // [4H] original layout
    const float* __restrict__ rowx,       // [B] or nullptr (layer-0 x)
    const float* __restrict__ colw,       // [4H] or nullptr (layer-0 Wx0)
    const float* __restrict__ c_prev,     // [B,H]
    float* __restrict__ c_out,            // [B,H]
    float* __restrict__ h_out,            // [B,H] or nullptr (dead for l<3)
    __half* __restrict__ nA,              // next-layer A or nullptr (dead for l=3)
    const float* __restrict__ Wd,         // [H] head weights (last layer) or nullptr
    float* __restrict__ pred)             // [B] head output (pre-init to bd)
{
    extern __shared__ char smem[];
    const uint32_t sb = smem_u32(smem);

    const int tid    = threadIdx.x;
    const int wid    = tid >> 5;
    const int lane   = tid & 31;
    const int warp_m = wid & 3;
    const int warp_n = wid >> 2;
    const int bm = blockIdx.y * 128;
    const int bn = blockIdx.x * 128;

    const uint32_t swz   = (uint32_t)(lane & 7) << 4;
    const int      arow  = lane & 15;
    const uint32_t acol  = (uint32_t)(lane >> 4) * 16;
    const int      brow  = ((lane >> 4) << 3) | (lane & 7);
    const uint32_t bcol  = (uint32_t)((lane >> 3) & 1) * 16;

    const uint32_t aRowOff = (uint32_t)(warp_m * 32 + arow) * ROWB;
    const uint32_t bRowOff = (uint32_t)(warp_n * 64 + brow) * ROWB;

    float acc[2][8][4];
    #pragma unroll
    for (int mt = 0; mt < 2; mt++)
        #pragma unroll
        for (int nt = 0; nt < 8; nt++)
            #pragma unroll
            for (int q = 0; q < 4; q++) acc[mt][nt][q] = 0.f;

    load_region(A,  bm, 0, sb + 0 * REG_B, tid);
    load_region(Wh, bn, 0, sb + 1 * REG_B, tid);
    cp_commit();

    for (int c = 0; c < NCHUNKS; ++c) {
        if (c + 1 < NCHUNKS) {
            const uint32_t sbuf = sb + ((c + 1) & 1) * STAGE_B;
            const int k0 = (c + 1) * KC;
            load_region(A,  bm, k0, sbuf, tid);
            load_region(Wh, bn, k0, sbuf + REG_B, tid);
            cp_commit();
            cp_wait<1>();
        } else {
            cp_wait<0>();
        }
        __syncthreads();

        const uint32_t base  = sb + (c & 1) * STAGE_B;
        const uint32_t aBase = base + aRowOff;
        const uint32_t bBase = base + REG_B + bRowOff;

        #pragma unroll
        for (int kk = 0; kk < 4; kk++) {
            const int ks = (kk + wid) & 3;
            const uint32_t ko = (uint32_t)ks * 32;          // 16 fp16 = 32 B
            const uint32_t aOff = (acol + ko) ^ swz;
            const uint32_t bOff = (bcol + ko) ^ swz;

            uint32_t ah[2][4], bh[4][4];
            #pragma unroll
            for (int np = 0; np < 4; np++)
                ldm_x4(bh[np], bBase + (uint32_t)np * 16 * ROWB + bOff);
            #pragma unroll
            for (int mt = 0; mt < 2; mt++)
                ldm_x4(ah[mt], aBase + (uint32_t)mt * 16 * ROWB + aOff);

            #pragma unroll
            for (int mt = 0; mt < 2; mt++)
                #pragma unroll
                for (int nt = 0; nt < 8; nt++)
                    mma16816(acc[mt][nt], ah[mt], &bh[nt >> 1][(nt & 1) * 2]);
        }
        __syncthreads();
    }

    // ---- epilogue phase 1: stage z tile to smem (row stride 528B) ----
    {
        const int quad = lane >> 2;
        const uint32_t ncol = (uint32_t)(warp_n * 64 + 2 * (lane & 3)) * 4;
        #pragma unroll
        for (int mt = 0; mt < 2; mt++) {
            const uint32_t m0 = (uint32_t)(warp_m * 32 + mt * 16 + quad);
            #pragma unroll
            for (int nt = 0; nt < 8; nt++) {
                const uint32_t a0 = sb + m0 * ZROWB + ncol + (uint32_t)nt * 32;
                sts64(a0,             acc[mt][nt][0], acc[mt][nt][1]);
                sts64(a0 + 8 * ZROWB, acc[mt][nt][2], acc[mt][nt][3]);
            }
        }
    }
    __syncthreads();

    // ---- epilogue phase 2: gates + cell update, fully coalesced gmem ----
    {
        const int jb   = tid & 7;            // j-block of 4
        const int mrow = tid >> 3;           // 0..31
        const int jcol = (bn >> 2) + jb * 4; // hidden index base (4 consecutive)

        const float4 bi = *(const float4*)(bias + 0 * HID + jcol);
        const float4 bf = *(const float4*)(bias + 1 * HID + jcol);
        const float4 bg = *(const float4*)(bias + 2 * HID + jcol);
        const float4 bo = *(const float4*)(bias + 3 * HID + jcol);
        float4 wi, wf, wg, wo;
        if (colw) {
            wi = *(const float4*)(colw + 0 * HID + jcol);
            wf = *(const float4*)(colw + 1 * HID + jcol);
            wg = *(const float4*)(colw + 2 * HID + jcol);
            wo = *(const float4*)(colw + 3 * HID + jcol);
        }
        float4 wd4;
        if (Wd) wd4 = *(const float4*)(Wd + jcol);

        #pragma unroll
        for (int mi = 0; mi < 4; mi++) {
            const int m_local = mrow + 32 * mi;
            const int m = bm + m_local;
            const uint32_t zb = sb + (uint32_t)m_local * ZROWB + (uint32_t)jb * 64;
            float4 z0 = lds128(zb);        // j+0: (zi,zf,zg,zo)
            float4 z1 = lds128(zb + 16);   // j+1
            float4 z2 = lds128(zb + 32);   // j+2
            float4 z3 = lds128(zb + 48);   // j+3

            const size_t gidx = (size_t)m * HID + jcol;
            const float4 cp = *(const float4*)(c_prev + gidx);
            const float xv = colw ? rowx[m] : 0.f;

            float zi[4] = {z0.x + bi.x, z1.x + bi.y, z2.x + bi.z, z3.x + bi.w};
            float zf[4] = {z0.y + bf.x, z1.y + bf.y, z2.y + bf.z, z3.y + bf.w};
            float zg[4] = {z0.z + bg.x, z1.z + bg.y, z2.z + bg.z, z3.z + bg.w};
            float zo[4] = {z0.w + bo.x, z1.w + bo.y, z2.w + bo.z, z3.w + bo.w};
            if (colw) {
                zi[0] = fmaf(xv, wi.x, zi[0]); zi[1] = fmaf(xv, wi.y, zi[1]);
                zi[2] = fmaf(xv, wi.z, zi[2]); zi[3] = fmaf(xv, wi.w, zi[3]);
                zf[0] = fmaf(xv, wf.x, zf[0]); zf[1] = fmaf(xv, wf.y, zf[1]);
                zf[2] = fmaf(xv, wf.z, zf[2]); zf[3] = fmaf(xv, wf.w, zf[3]);
                zg[0] = fmaf(xv, wg.x, zg[0]); zg[1] = fmaf(xv, wg.y, zg[1]);
                zg[2] = fmaf(xv, wg.z, zg[2]); zg[3] = fmaf(xv, wg.w, zg[3]);
                zo[0] = fmaf(xv, wo.x, zo[0]); zo[1] = fmaf(xv, wo.y, zo[1]);
                zo[2] = fmaf(xv, wo.z, zo[2]); zo[3] = fmaf(xv, wo.w, zo[3]);
            }
            const float cpv[4] = {cp.x, cp.y, cp.z, cp.w};
            float4 co, ho;
            float* cop = &co.x;
            float* hop = &ho.x;
            __half hv[4];
            #pragma unroll
            for (int q = 0; q < 4; q++) {
                const float ig = fsigmoid(zi[q]);
                const float fg = fsigmoid(zf[q]);
                const float gg = ftanh(zg[q]);
                const float og = fsigmoid(zo[q]);
                const float cc = fmaf(fg, cpv[q], ig * gg);
                const float hh = og * ftanh(cc);
                cop[q] = cc;
                hop[q] = hh;
                hv[q] = __float2half_rn(hh);
            }
            *(float4*)(c_out + gidx) = co;
            if (h_out) *(float4*)(h_out + gidx) = ho;
            if (nA)
                *(uint2*)(nA + gidx) = make_uint2(
                    (uint32_t)__half_as_ushort(hv[0]) | ((uint32_t)__half_as_ushort(hv[1]) << 16),
                    (uint32_t)__half_as_ushort(hv[2]) | ((uint32_t)__half_as_ushort(hv[3]) << 16));
            if (Wd) {
                float p = ho.x * wd4.x + ho.y * wd4.y + ho.z * wd4.z + ho.w * wd4.w;
                p += __shfl_down_sync(0xffffffffu, p, 4, 8);
                p += __shfl_down_sync(0xffffffffu, p, 2, 8);
                p += __shfl_down_sync(0xffffffffu, p, 1, 8);
                if (jb == 0) atomicAdd(&pred[m], p);
            }
        }
    }
}

// ---------------------------------------------------------------------------
// Prep (ONE launch, gridDim.z = 5):
//  z<4 : weight prep layer z — coalesced transpose + gate-permute + sum + fp16
//  z==4: h0 fp32->fp16 convert, and pred init to bd[0]
// ---------------------------------------------------------------------------
__global__ void prep(const float* __restrict__ Wh0,
                     const float* __restrict__ Wx, const float* __restrict__ Whh,
                     __half* __restrict__ wout,
                     const float* __restrict__ h0, __half* __restrict__ A0,
                     const float* __restrict__ bd, float* __restrict__ pred)
{
    const int l  = blockIdx.z;
    const int tx = threadIdx.x, ty = threadIdx.y;

    if (l < NLAYERS) {
        __shared__ float s[32][33];
        const int k0 = blockIdx.x * 32;
        const int c0 = blockIdx.y * 32;
        float v;
        if (l == 0) {
            v = Wh0[(size_t)(k0 + ty) * FOURH + c0 + tx];
        } else {
            const size_t off = (size_t)(l - 1) * HID * FOURH + (size_t)(k0 + ty) * FOURH + c0 + tx;
            v = Wx[off] + Whh[off];
        }
        s[ty][tx] = v;
        __syncthreads();
        const int n = 4 * ((c0 & (HID - 1)) + ty) + (c0 >> 10);
        wout[(size_t)l * FOURH * HID + (size_t)n * HID + k0 + tx] =
            __float2half_rn(s[tx][ty]);
    } else {
        const int bid = blockIdx.x + 32 * blockIdx.y;   // 0..4095
        const int t   = ty * 32 + tx;                   // 0..1023
        if (bid < 2048) {
            const size_t i = (size_t)bid * 1024 + t;    // covers B*H/4 float4s
            float4 v = ((const float4*)h0)[i];
            uint32_t p0 = (uint32_t)__half_as_ushort(__float2half_rn(v.x))
                        | ((uint32_t)__half_as_ushort(__float2half_rn(v.y)) << 16);
            uint32_t p1 = (uint32_t)__half_as_ushort(__float2half_rn(v.z))
                        | ((uint32_t)__half_as_ushort(__float2half_rn(v.w)) << 16);
            ((uint2*)A0)[i] = make_uint2(p0, p1);
        } else if (bid < 2056) {
            const int b = (bid - 2048) * 1024 + t;      // covers BATCH
            pred[b] = bd[0];
        }
    }
}

// ---------------------------------------------------------------------------
extern "C" void kernel_launch(void* const* d_in, const int* in_sizes, int n_in,
                              void* d_out, int out_size)
{
    const float* x_todec = (const float*)d_in[0];
    const float* c0      = (const float*)d_in[1];
    const float* h0      = (const float*)d_in[2];
    const float* Wx0     = (const float*)d_in[3];
    const float* Wh0     = (const float*)d_in[4];
    const float* b0      = (const float*)d_in[5];
    const float* Wx      = (const float*)d_in[6];
    const float* Wh      = (const float*)d_in[7];
    const float* bl      = (const float*)d_in[8];
    const float* Wd      = (const float*)d_in[9];
    const float* bd      = (const float*)d_in[10];

    float* out  = (float*)d_out;
    float* cbuf = out;
    float* hbuf = out + (size_t)BATCH * HID;
    float* pred = out + 2 * (size_t)BATCH * HID;

    __half *A0, *A1, *W16;
    cudaGetSymbolAddress((void**)&A0, g_A0);
    cudaGetSymbolAddress((void**)&A1, g_A1);
    cudaGetSymbolAddress((void**)&W16, g_W16);

    static bool attr_set = false;
    if (!attr_set) {
        cudaFuncSetAttribute(gemm_lstm_fused,
                             cudaFuncAttributeMaxDynamicSharedMemorySize, GEMM_SMEM);
        attr_set = true;
    }

    const dim3 ggrid(FOURH / 128, BATCH / 128);   // (32,64)

    // one prep launch: weights (4 layers) + h0 convert + pred=bd init
    prep<<<dim3(HID / 32, FOURH / 32, NLAYERS + 1), dim3(32, 32)>>>(
        Wh0, Wx, Wh, W16, h0, A0, bd, pred);

    // layer 0: z = h0 @ Wh0^T (+ x*Wx0 + b0 in epilogue); h_out dead
    gemm_lstm_fused<<<ggrid, 256, GEMM_SMEM>>>(A0, W16,
                                               b0, x_todec, Wx0,
                                               c0, cbuf, nullptr, A1,
                                               nullptr, nullptr);
    // layer 1
    gemm_lstm_fused<<<ggrid, 256, GEMM_SMEM>>>(A1, W16 + 1 * (size_t)FOURH * HID,
                                               bl + 0 * FOURH, nullptr, nullptr,
                                               cbuf, cbuf, nullptr, A0,
                                               nullptr, nullptr);
    // layer 2
    gemm_lstm_fused<<<ggrid, 256, GEMM_SMEM>>>(A0, W16 + 2 * (size_t)FOURH * HID,
                                               bl + 1 * FOURH, nullptr, nullptr,
                                               cbuf, cbuf, nullptr, A1,
                                               nullptr, nullptr);
    // layer 3: h_out live, nA dead, fused head
    gemm_lstm_fused<<<ggrid, 256, GEMM_SMEM>>>(A1, W16 + 3 * (size_t)FOURH * HID,
                                               bl + 2 * FOURH, nullptr, nullptr,
                                               cbuf, cbuf, hbuf, nullptr,
                                               Wd, pred);
}

// round 15
// speedup vs baseline: 1.4217x; 1.0016x over previous
#include <cuda_runtime.h>
#include <cuda_fp16.h>
#include <cstdint>
#include <math.h>

#define BATCH 8192
#define HID   1024
#define FOURH 4096
#define NLAYERS 4

// ---------------------------------------------------------------------------
// Scratch (allocation-free). Ping-pong activation buffers (cross-CTA safety).
// ---------------------------------------------------------------------------
__device__ __half g_A0[(size_t)BATCH * HID];
__device__ __half g_A1[(size_t)BATCH * HID];
__device__ __half g_W16[(size_t)NLAYERS * FOURH * HID];   // gate-permuted, transposed

// ---------------------------------------------------------------------------
// PTX helpers (arch-agnostic: sm_80+)
// ---------------------------------------------------------------------------
__device__ __forceinline__ uint32_t smem_u32(const void* p) {
    uint32_t a;
    asm("{ .reg .u64 t; cvta.to.shared.u64 t, %1; cvt.u32.u64 %0, t; }" : "=r"(a) : "l"(p));
    return a;
}
__device__ __forceinline__ void cp_async16(uint32_t sdst, const void* gsrc) {
    asm volatile("cp.async.cg.shared.global [%0], [%1], 16;" :: "r"(sdst), "l"(gsrc));
}
__device__ __forceinline__ void cp_commit() { asm volatile("cp.async.commit_group;"); }
template <int N>
__device__ __forceinline__ void cp_wait() { asm volatile("cp.async.wait_group %0;" :: "n"(N)); }

__device__ __forceinline__ void ldm_x4(uint32_t* r, uint32_t addr) {
    asm volatile("ldmatrix.sync.aligned.m8n8.x4.shared.b16 {%0,%1,%2,%3}, [%4];"
                 : "=r"(r[0]), "=r"(r[1]), "=r"(r[2]), "=r"(r[3]) : "r"(addr));
}
__device__ __forceinline__ void mma16816(float* c, const uint32_t* a, const uint32_t* b) {
    asm("mma.sync.aligned.m16n8k16.row.col.f32.f16.f16.f32 "
        "{%0,%1,%2,%3}, {%4,%5,%6,%7}, {%8,%9}, {%0,%1,%2,%3};"
        : "+f"(c[0]), "+f"(c[1]), "+f"(c[2]), "+f"(c[3])
        : "r"(a[0]), "r"(a[1]), "r"(a[2]), "r"(a[3]), "r"(b[0]), "r"(b[1]));
}
__device__ __forceinline__ void sts64(uint32_t addr, float x, float y) {
    asm volatile("st.shared.v2.f32 [%0], {%1, %2};" :: "r"(addr), "f"(x), "f"(y));
}
__device__ __forceinline__ float4 lds128(uint32_t addr) {
    float4 v;
    asm volatile("ld.shared.v4.f32 {%0,%1,%2,%3}, [%4];"
                 : "=f"(v.x), "=f"(v.y), "=f"(v.z), "=f"(v.w) : "r"(addr));
    return v;
}

// Fast transcendentals (bounded args; error ~1e-7 — negligible vs 2.6e-4 budget)
__device__ __forceinline__ float fsigmoid(float z) {
    return __fdividef(1.f, 1.f + __expf(-z));
}
__device__ __forceinline__ float ftanh(float x) {
    const float t = __expf(-2.f * x);
    return __fdividef(1.f - t, 1.f + t);
}

// ---------------------------------------------------------------------------
// GEMM + fused LSTM gate epilogue + fused next-layer fp16 convert
// + (last layer) fused prediction head via atomicAdd partials.
// C = A @ W16^T, single fp16 product. CTA tile 128x128, 8 warps (4Mx2N),
// warp tile 32x64. 2 CTAs/SM, double-buffered K chunks of 64 fp16,
// XOR-swizzled 128B rows (c -> c ^ (row&7)).
// Mainloop is at the smem-crossbar floor (~2048 wf/chunk/SM) — do not touch.
// ---------------------------------------------------------------------------
#define KC        64
#define NCHUNKS   (HID / KC)               // 16
#define ROWB      128
#define REG_B     (128 * ROWB)             // 16384 B per region
#define STAGE_B   (2 * REG_B)              // 32768 B (A, W)
#define ZROWB     528                      // epilogue fp32 row stride
#define GEMM_SMEM (128 * ZROWB)            // 67584 B (mainloop uses 65536)

__device__ __forceinline__ void load_region(const __half* g, int row0, int k0,
                                            uint32_t sdst, int tid) {
    const int row  = tid >> 1;
    const int half = tid & 1;
    const __half* src = g + (size_t)(row0 + row) * HID + k0 + half * 32;
    const uint32_t rbase = sdst + (uint32_t)row * ROWB;
    const int rm = row & 7;
    #pragma unroll
    for (int q = 0; q < 4; q++) {
        const int chunk = half * 4 + q;
        cp_async16(rbase + (uint32_t)((chunk ^ rm) << 4), src + q * 8);
    }
}

__global__ __launch_bounds__(256, 2) void gemm_lstm_fused(
    const __half* __restrict__ A,
    const __half* __restrict__ Wh,
    const float* __restrict__ bias,       // [4H] original layout
    const float* __restrict__ rowx,       // [B] or nullptr (layer-0 x)
    const float* __restrict__ colw,       // [4H] or nullptr (layer-0 Wx0)
    const float* __restrict__ c_prev,     // [B,H]
    float* __restrict__ c_out,            // [B,H]
    float* __restrict__ h_out,            // [B,H] or nullptr (dead for l<3)
    __half* __restrict__ nA,              // next-layer A or nullptr (dead for l=3)
    const float* __restrict__ Wd,         // [H] head weights (last layer) or nullptr
    float* __restrict__ pred)             // [B] head output (pre-init to bd)
{
    extern __shared__ char smem[];
    const uint32_t sb = smem_u32(smem);

    const int tid    = threadIdx.x;
    const int wid    = tid >> 5;
    const int lane   = tid & 31;
    const int warp_m = wid & 3;
    const int warp_n = wid >> 2;
    const int bm = blockIdx.y * 128;
    const int bn = blockIdx.x * 128;

    const uint32_t swz   = (uint32_t)(lane & 7) << 4;
    const int      arow  = lane & 15;
    const uint32_t acol  = (uint32_t)(lane >> 4) * 16;
    const int      brow  = ((lane >> 4) << 3) | (lane & 7);
    const uint32_t bcol  = (uint32_t)((lane >> 3) & 1) * 16;

    const uint32_t aRowOff = (uint32_t)(warp_m * 32 + arow) * ROWB;
    const uint32_t bRowOff = (uint32_t)(warp_n * 64 + brow) * ROWB;

    float acc[2][8][4];
    #pragma unroll
    for (int mt = 0; mt < 2; mt++)
        #pragma unroll
        for (int nt = 0; nt < 8; nt++)
            #pragma unroll
            for (int q = 0; q < 4; q++) acc[mt][nt][q] = 0.f;

    load_region(A,  bm, 0, sb + 0 * REG_B, tid);
    load_region(Wh, bn, 0, sb + 1 * REG_B, tid);
    cp_commit();

    for (int c = 0; c < NCHUNKS; ++c) {
        if (c + 1 < NCHUNKS) {
            const uint32_t sbuf = sb + ((c + 1) & 1) * STAGE_B;
            const int k0 = (c + 1) * KC;
            load_region(A,  bm, k0, sbuf, tid);
            load_region(Wh, bn, k0, sbuf + REG_B, tid);
            cp_commit();
            cp_wait<1>();
        } else {
            cp_wait<0>();
        }
        __syncthreads();

        const uint32_t base  = sb + (c & 1) * STAGE_B;
        const uint32_t aBase = base + aRowOff;
        const uint32_t bBase = base + REG_B + bRowOff;

        #pragma unroll
        for (int kk = 0; kk < 4; kk++) {
            const int ks = (kk + wid) & 3;
            const uint32_t ko = (uint32_t)ks * 32;          // 16 fp16 = 32 B
            const uint32_t aOff = (acol + ko) ^ swz;
            const uint32_t bOff = (bcol + ko) ^ swz;

            uint32_t ah[2][4], bh[4][4];
            #pragma unroll
            for (int np = 0; np < 4; np++)
                ldm_x4(bh[np], bBase + (uint32_t)np * 16 * ROWB + bOff);
            #pragma unroll
            for (int mt = 0; mt < 2; mt++)
                ldm_x4(ah[mt], aBase + (uint32_t)mt * 16 * ROWB + aOff);

            #pragma unroll
            for (int mt = 0; mt < 2; mt++)
                #pragma unroll
                for (int nt = 0; nt < 8; nt++)
                    mma16816(acc[mt][nt], ah[mt], &bh[nt >> 1][(nt & 1) * 2]);
        }
        __syncthreads();
    }

    // ---- epilogue phase 1: stage z tile to smem (row stride 528B) ----
    {
        const int quad = lane >> 2;
        const uint32_t ncol = (uint32_t)(warp_n * 64 + 2 * (lane & 3)) * 4;
        #pragma unroll
        for (int mt = 0; mt < 2; mt++) {
            const uint32_t m0 = (uint32_t)(warp_m * 32 + mt * 16 + quad);
            #pragma unroll
            for (int nt = 0; nt < 8; nt++) {
                const uint32_t a0 = sb + m0 * ZROWB + ncol + (uint32_t)nt * 32;
                sts64(a0,             acc[mt][nt][0], acc[mt][nt][1]);
                sts64(a0 + 8 * ZROWB, acc[mt][nt][2], acc[mt][nt][3]);
            }
        }
    }
    __syncthreads();

    // ---- epilogue phase 2: gates + cell update, fully coalesced gmem ----
    {
        const int jb   = tid & 7;            // j-block of 4
        const int mrow = tid >> 3;           // 0..31
        const int jcol = (bn >> 2) + jb * 4; // hidden index base (4 consecutive)

        const float4 bi = *(const float4*)(bias + 0 * HID + jcol);
        const float4 bf = *(const float4*)(bias + 1 * HID + jcol);
        const float4 bg = *(const float4*)(bias + 2 * HID + jcol);
        const float4 bo = *(const float4*)(bias + 3 * HID + jcol);
        float4 wi, wf, wg, wo;
        if (colw) {
            wi = *(const float4*)(colw + 0 * HID + jcol);
            wf = *(const float4*)(colw + 1 * HID + jcol);
            wg = *(const float4*)(colw + 2 * HID + jcol);
            wo = *(const float4*)(colw + 3 * HID + jcol);
        }
        float4 wd4;
        if (Wd) wd4 = *(const float4*)(Wd + jcol);

        #pragma unroll
        for (int mi = 0; mi < 4; mi++) {
            const int m_local = mrow + 32 * mi;
            const int m = bm + m_local;
            const uint32_t zb = sb + (uint32_t)m_local * ZROWB + (uint32_t)jb * 64;
            float4 z0 = lds128(zb);        // j+0: (zi,zf,zg,zo)
            float4 z1 = lds128(zb + 16);   // j+1
            float4 z2 = lds128(zb + 32);   // j+2
            float4 z3 = lds128(zb + 48);   // j+3

            const size_t gidx = (size_t)m * HID + jcol;
            const float4 cp = *(const float4*)(c_prev + gidx);
            const float xv = colw ? rowx[m] : 0.f;

            float zi[4] = {z0.x + bi.x, z1.x + bi.y, z2.x + bi.z, z3.x + bi.w};
            float zf[4] = {z0.y + bf.x, z1.y + bf.y, z2.y + bf.z, z3.y + bf.w};
            float zg[4] = {z0.z + bg.x, z1.z + bg.y, z2.z + bg.z, z3.z + bg.w};
            float zo[4] = {z0.w + bo.x, z1.w + bo.y, z2.w + bo.z, z3.w + bo.w};
            if (colw) {
                zi[0] = fmaf(xv, wi.x, zi[0]); zi[1] = fmaf(xv, wi.y, zi[1]);
                zi[2] = fmaf(xv, wi.z, zi[2]); zi[3] = fmaf(xv, wi.w, zi[3]);
                zf[0] = fmaf(xv, wf.x, zf[0]); zf[1] = fmaf(xv, wf.y, zf[1]);
                zf[2] = fmaf(xv, wf.z, zf[2]); zf[3] = fmaf(xv, wf.w, zf[3]);
                zg[0] = fmaf(xv, wg.x, zg[0]); zg[1] = fmaf(xv, wg.y, zg[1]);
                zg[2] = fmaf(xv, wg.z, zg[2]); zg[3] = fmaf(xv, wg.w, zg[3]);
                zo[0] = fmaf(xv, wo.x, zo[0]); zo[1] = fmaf(xv, wo.y, zo[1]);
                zo[2] = fmaf(xv, wo.z, zo[2]); zo[3] = fmaf(xv, wo.w, zo[3]);
            }
            const float cpv[4] = {cp.x, cp.y, cp.z, cp.w};
            float4 co, ho;
            float* cop = &co.x;
            float* hop = &ho.x;
            __half hv[4];
            #pragma unroll
            for (int q = 0; q < 4; q++) {
                const float ig = fsigmoid(zi[q]);
                const float fg = fsigmoid(zf[q]);
                const float gg = ftanh(zg[q]);
                const float og = fsigmoid(zo[q]);
                const float cc = fmaf(fg, cpv[q], ig * gg);
                const float hh = og * ftanh(cc);
                cop[q] = cc;
                hop[q] = hh;
                hv[q] = __float2half_rn(hh);
            }
            *(float4*)(c_out + gidx) = co;
            if (h_out) *(float4*)(h_out + gidx) = ho;
            if (nA)
                *(uint2*)(nA + gidx) = make_uint2(
                    (uint32_t)__half_as_ushort(hv[0]) | ((uint32_t)__half_as_ushort(hv[1]) << 16),
                    (uint32_t)__half_as_ushort(hv[2]) | ((uint32_t)__half_as_ushort(hv[3]) << 16));
            if (Wd) {
                float p = ho.x * wd4.x + ho.y * wd4.y + ho.z * wd4.z + ho.w * wd4.w;
                p += __shfl_down_sync(0xffffffffu, p, 4, 8);
                p += __shfl_down_sync(0xffffffffu, p, 2, 8);
                p += __shfl_down_sync(0xffffffffu, p, 1, 8);
                if (jb == 0) atomicAdd(&pred[m], p);
            }
        }
    }
}

// ---------------------------------------------------------------------------
// prep1 (main stream, GEMM0's true dependency):
//  z==0: layer-0 weight transform (transpose + gate-permute + fp16)
//  z==1: h0 fp32->fp16 convert + pred init to bd[0]
// ---------------------------------------------------------------------------
__global__ void prep1(const float* __restrict__ Wh0, __half* __restrict__ wout,
                      const float* __restrict__ h0, __half* __restrict__ A0,
                      const float* __restrict__ bd, float* __restrict__ pred)
{
    const int tx = threadIdx.x, ty = threadIdx.y;
    if (blockIdx.z == 0) {
        __shared__ float s[32][33];
        const int k0 = blockIdx.x * 32;
        const int c0 = blockIdx.y * 32;
        s[ty][tx] = Wh0[(size_t)(k0 + ty) * FOURH + c0 + tx];
        __syncthreads();
        const int n = 4 * ((c0 & (HID - 1)) + ty) + (c0 >> 10);
        wout[(size_t)n * HID + k0 + tx] = __float2half_rn(s[tx][ty]);
    } else {
        const int bid = blockIdx.x + 32 * blockIdx.y;   // 0..4095
        const int t   = ty * 32 + tx;                   // 0..1023
        if (bid < 2048) {
            const size_t i = (size_t)bid * 1024 + t;    // covers B*H/4 float4s
            float4 v = ((const float4*)h0)[i];
            uint32_t p0 = (uint32_t)__half_as_ushort(__float2half_rn(v.x))
                        | ((uint32_t)__half_as_ushort(__float2half_rn(v.y)) << 16);
            uint32_t p1 = (uint32_t)__half_as_ushort(__float2half_rn(v.z))
                        | ((uint32_t)__half_as_ushort(__float2half_rn(v.w)) << 16);
            ((uint2*)A0)[i] = make_uint2(p0, p1);
        } else if (bid < 2056) {
            const int b = (bid - 2048) * 1024 + t;      // covers BATCH
            pred[b] = bd[0];
        }
    }
}

// ---------------------------------------------------------------------------
// prep2 (side stream, overlaps GEMM0): layers 1..3 weight transform:
// sum Wx+Wh, transpose, gate-permute, fp16. z = layer-1.
// ---------------------------------------------------------------------------
__global__ void prep2(const float* __restrict__ Wx, const float* __restrict__ Whh,
                      __half* __restrict__ wout)
{
    __shared__ float s[32][33];
    const int l  = blockIdx.z + 1;
    const int k0 = blockIdx.x * 32;
    const int c0 = blockIdx.y * 32;
    const int tx = threadIdx.x, ty = threadIdx.y;
    const size_t off = (size_t)(l - 1) * HID * FOURH + (size_t)(k0 + ty) * FOURH + c0 + tx;
    s[ty][tx] = Wx[off] + Whh[off];
    __syncthreads();
    const int n = 4 * ((c0 & (HID - 1)) + ty) + (c0 >> 10);
    wout[(size_t)l * FOURH * HID + (size_t)n * HID + k0 + tx] =
        __float2half_rn(s[tx][ty]);
}

// ---------------------------------------------------------------------------
extern "C" void kernel_launch(void* const* d_in, const int* in_sizes, int n_in,
                              void* d_out, int out_size)
{
    const float* x_todec = (const float*)d_in[0];
    const float* c0      = (const float*)d_in[1];
    const float* h0      = (const float*)d_in[2];
    const float* Wx0     = (const float*)d_in[3];
    const float* Wh0     = (const float*)d_in[4];
    const float* b0      = (const float*)d_in[5];
    const float* Wx      = (const float*)d_in[6];
    const float* Wh      = (const float*)d_in[7];
    const float* bl      = (const float*)d_in[8];
    const float* Wd      = (const float*)d_in[9];
    const float* bd      = (const float*)d_in[10];

    float* out  = (float*)d_out;
    float* cbuf = out;
    float* hbuf = out + (size_t)BATCH * HID;
    float* pred = out + 2 * (size_t)BATCH * HID;

    __half *A0, *A1, *W16;
    cudaGetSymbolAddress((void**)&A0, g_A0);
    cudaGetSymbolAddress((void**)&A1, g_A1);
    cudaGetSymbolAddress((void**)&W16, g_W16);

    static bool init_done = false;
    static cudaStream_t s2;
    static cudaEvent_t ev_fork, ev_join;
    if (!init_done) {
        cudaFuncSetAttribute(gemm_lstm_fused,
                             cudaFuncAttributeMaxDynamicSharedMemorySize, GEMM_SMEM);
        cudaStreamCreateWithFlags(&s2, cudaStreamNonBlocking);
        cudaEventCreateWithFlags(&ev_fork, cudaEventDisableTiming);
        cudaEventCreateWithFlags(&ev_join, cudaEventDisableTiming);
        init_done = true;
    }

    const dim3 ggrid(FOURH / 128, BATCH / 128);   // (32,64)

    // prep1 on main stream: layer-0 weights + h0 convert + pred=bd
    prep1<<<dim3(HID / 32, FOURH / 32, 2), dim3(32, 32)>>>(Wh0, W16, h0, A0, bd, pred);

    // fork: prep2 (layers 1-3 weights) on side stream, overlapping GEMM0
    cudaEventRecord(ev_fork, 0);
    cudaStreamWaitEvent(s2, ev_fork, 0);
    prep2<<<dim3(HID / 32, FOURH / 32, 3), dim3(32, 32), 0, s2>>>(Wx, Wh, W16);
    cudaEventRecord(ev_join, s2);

    // layer 0: z = h0 @ Wh0^T (+ x*Wx0 + b0 in epilogue); h_out dead
    gemm_lstm_fused<<<ggrid, 256, GEMM_SMEM>>>(A0, W16,
                                               b0, x_todec, Wx0,
                                               c0, cbuf, nullptr, A1,
                                               nullptr, nullptr);

    // join: layers 1-3 weights must be ready
    cudaStreamWaitEvent(0, ev_join, 0);

    // layer 1
    gemm_lstm_fused<<<ggrid, 256, GEMM_SMEM>>>(A1, W16 + 1 * (size_t)FOURH * HID,
                                               bl + 0 * FOURH, nullptr, nullptr,
                                               cbuf, cbuf, nullptr, A0,
                                               nullptr, nullptr);
    // layer 2
    gemm_lstm_fused<<<ggrid, 256, GEMM_SMEM>>>(A0, W16 + 2 * (size_t)FOURH * HID,
                                               bl + 1 * FOURH, nullptr, nullptr,
                                               cbuf, cbuf, nullptr, A1,
                                               nullptr, nullptr);
    // layer 3: h_out live, nA dead, fused head
    gemm_lstm_fused<<<ggrid, 256, GEMM_SMEM>>>(A1, W16 + 3 * (size_t)FOURH * HID,
                                               bl + 2 * FOURH, nullptr, nullptr,
                                               cbuf, cbuf, hbuf, nullptr,
                                               Wd, pred);
}